// round 8
// baseline (speedup 1.0000x reference)
#include <cuda_runtime.h>
#include <cuda_fp16.h>
#include <cstdint>

#define Bn 4
#define Sn 80
#define Pn 6500
#define Hdim 128
#define PSPLIT 13
#define PCHUNK 500    // 13 * 500 = 6500 exactly
#define NT1 4         // ceil(500/128)
#define RS 35         // SMEM row stride in 32-bit words — conflict-free
#define NEGBIG (-1.0e30f)

// ---------------- scratch ----------------
__device__ float d_embpart[PSPLIT][Bn * Sn][128];
__device__ float d_xg[2][Bn][Sn][4 * Hdim];
__device__ float d_hfinal[2][Bn][Hdim];

// ---------------- helpers ----------------
__device__ __forceinline__ uint32_t smem_u32_(const void* p) {
    return (uint32_t)__cvta_generic_to_shared(p);
}
__device__ __forceinline__ uint32_t mapa_rank_(uint32_t a, uint32_t r) {
    uint32_t d;
    asm("mapa.shared::cluster.u32 %0, %1, %2;" : "=r"(d) : "r"(a), "r"(r));
    return d;
}
__device__ __forceinline__ void stc_f32_(uint32_t a, float v) {
    asm volatile("st.shared::cluster.f32 [%0], %1;" :: "r"(a), "f"(v) : "memory");
}
__device__ __forceinline__ void cluster_sync_() {
    asm volatile("barrier.cluster.arrive.aligned;" ::: "memory");
    asm volatile("barrier.cluster.wait.aligned;" ::: "memory");
}
__device__ __forceinline__ float sigmoid_(float x) { return 1.0f / (1.0f + expf(-x)); }

// pack two fp32 -> f16x2 word (v0 in low half)
__device__ __forceinline__ uint32_t packh2_(float v0, float v1) {
    __half2 h = __floats2half2_rn(v0, v1);
    return *reinterpret_cast<uint32_t*>(&h);
}

// m16n8k16 fp16 MMA, fp32 accumulate in-place
#define MMA_(c, a, b0v, b1v) \
    asm volatile("mma.sync.aligned.m16n8k16.row.col.f32.f16.f16.f32 " \
        "{%0,%1,%2,%3}, {%4,%5,%6,%7}, {%8,%9}, {%0,%1,%2,%3};" \
        : "+f"((c)[0]), "+f"((c)[1]), "+f"((c)[2]), "+f"((c)[3]) \
        : "r"((a)[0]), "r"((a)[1]), "r"((a)[2]), "r"((a)[3]), "r"(b0v), "r"(b1v))

// packed f32x2 fma (Blackwell)
__device__ __forceinline__ void fma2_(uint64_t& acc, uint64_t a, uint64_t b) {
    asm("fma.rn.f32x2 %0, %1, %2, %0;" : "+l"(acc) : "l"(a), "l"(b));
}

// =============================================================================
// Kernel 1: per-point MLP (2->64->128) + masked max, single-pass fp16 HMMA,
// double-buffered. grid (B*S, PSPLIT), 128 threads (4 warps).
// Epilogue stores max_p (acc + maskadd); bias+relu deferred to k2 (monotone).
// =============================================================================
__global__ __launch_bounds__(128) void k1_mma(
    const float* __restrict__ slices, const float* __restrict__ pmask,
    const float* __restrict__ W1, const float* __restrict__ b1,
    const float* __restrict__ W2)
{
    __shared__ uint32_t Bf[2][128 * RS];   // f16x2 point tiles (buf0 also W2 staging)
    __shared__ float mskS[2][128];         // maskadd: 0 or -1e30
    __shared__ float w1x[64], w1y[64], b1s[64];

    const int tid  = threadIdx.x;
    const int lane = tid & 31, w = tid >> 5;
    const int g = lane >> 2, ctid = lane & 3;
    const int bs = blockIdx.x;

    if (tid < 64) { w1x[tid] = W1[2 * tid]; w1y[tid] = W1[2 * tid + 1]; b1s[tid] = b1[tid]; }

    // ---- stage W2 fp16 into buffer 0 (scratch) ----
    {
        const float* wr = W2 + (size_t)tid * 64;
#pragma unroll 8
        for (int k = 0; k < 64; k += 2)
            Bf[0][tid * RS + (k >> 1)] = packh2_(wr[k], wr[k + 1]);
    }
    __syncthreads();

    // ---- A fragments (W2 fp16) into registers: [mtile][kstep][4] ----
    uint32_t Ah[2][4][4];
#pragma unroll
    for (int mt = 0; mt < 2; mt++) {
        int rA = w * 32 + mt * 16 + g;
#pragma unroll
        for (int ks = 0; ks < 4; ks++) {
            int base = rA * RS + ks * 8 + ctid;
            Ah[mt][ks][0] = Bf[0][base];
            Ah[mt][ks][1] = Bf[0][base + 8 * RS];
            Ah[mt][ks][2] = Bf[0][base + 4];
            Ah[mt][ks][3] = Bf[0][base + 8 * RS + 4];
        }
    }
    __syncthreads();   // staging done; buffers become point tiles

    const float* sp = slices + (size_t)bs * Pn * 2;
    const float* mp = pmask + (size_t)bs * Pn;
    const int pbeg = blockIdx.y * PCHUNK;
    const int pend = pbeg + PCHUNK;   // 13*500 = 6500 exactly

    // producer: layer-1 + fp16 pack for one 128-pt tile into buffer buf
    auto produce = [&](int tile, int buf) {
        const int p = pbeg + tile * 128 + tid;
        float x = 0.f, y = 0.f, ma = NEGBIG;
        if (p < pend) {
            float2 xy = *(const float2*)(sp + 2 * p);
            x = xy.x; y = xy.y;
            if (mp[p] > 0.f) ma = 0.f;
        }
        mskS[buf][tid] = ma;
        uint32_t* br = &Bf[buf][tid * RS];
#pragma unroll 8
        for (int k = 0; k < 64; k += 2) {
            float v0 = fmaxf(fmaf(w1x[k],     x, fmaf(w1y[k],     y, b1s[k])),     0.f);
            float v1 = fmaxf(fmaf(w1x[k + 1], x, fmaf(w1y[k + 1], y, b1s[k + 1])), 0.f);
            br[k >> 1] = packh2_(v0, v1);
        }
    };

    float wmax[2][2] = {{NEGBIG, NEGBIG}, {NEGBIG, NEGBIG}};

    produce(0, 0);
    __syncthreads();

    for (int tile = 0; tile < NT1; ++tile) {
        const int cur = tile & 1, nxt = cur ^ 1;
        if (tile + 1 < NT1) produce(tile + 1, nxt);

        const uint32_t* Bp = Bf[cur];
        const float* msk = mskS[cur];

        // two point-blocks per iteration -> 4 independent accumulator chains
#pragma unroll 2
        for (int nbp = 0; nbp < 8; ++nbp) {
            float cA0[4] = {0.f, 0.f, 0.f, 0.f};
            float cA1[4] = {0.f, 0.f, 0.f, 0.f};
            float cB0[4] = {0.f, 0.f, 0.f, 0.f};
            float cB1[4] = {0.f, 0.f, 0.f, 0.f};
            const int nrA = nbp * 16 + g;
            const int nrB = nrA + 8;
#pragma unroll
            for (int ks = 0; ks < 4; ++ks) {
                int ia = nrA * RS + ks * 8 + ctid;
                int ib = nrB * RS + ks * 8 + ctid;
                uint32_t a0 = Bp[ia], a1 = Bp[ia + 4];
                uint32_t b0 = Bp[ib], b1 = Bp[ib + 4];
                MMA_(cA0, Ah[0][ks], a0, a1);
                MMA_(cB0, Ah[0][ks], b0, b1);
                MMA_(cA1, Ah[1][ks], a0, a1);
                MMA_(cB1, Ah[1][ks], b0, b1);
            }
            // epilogue: max of (acc + maskadd); bias/relu deferred to k2
            float2 mA = *(const float2*)&msk[nbp * 16 + ctid * 2];
            float2 mB = *(const float2*)&msk[nbp * 16 + 8 + ctid * 2];
            wmax[0][0] = fmaxf(wmax[0][0], cA0[0] + mA.x);
            wmax[0][0] = fmaxf(wmax[0][0], cA0[1] + mA.y);
            wmax[0][1] = fmaxf(wmax[0][1], cA0[2] + mA.x);
            wmax[0][1] = fmaxf(wmax[0][1], cA0[3] + mA.y);
            wmax[1][0] = fmaxf(wmax[1][0], cA1[0] + mA.x);
            wmax[1][0] = fmaxf(wmax[1][0], cA1[1] + mA.y);
            wmax[1][1] = fmaxf(wmax[1][1], cA1[2] + mA.x);
            wmax[1][1] = fmaxf(wmax[1][1], cA1[3] + mA.y);
            wmax[0][0] = fmaxf(wmax[0][0], cB0[0] + mB.x);
            wmax[0][0] = fmaxf(wmax[0][0], cB0[1] + mB.y);
            wmax[0][1] = fmaxf(wmax[0][1], cB0[2] + mB.x);
            wmax[0][1] = fmaxf(wmax[0][1], cB0[3] + mB.y);
            wmax[1][0] = fmaxf(wmax[1][0], cB1[0] + mB.x);
            wmax[1][0] = fmaxf(wmax[1][0], cB1[1] + mB.y);
            wmax[1][1] = fmaxf(wmax[1][1], cB1[2] + mB.x);
            wmax[1][1] = fmaxf(wmax[1][1], cB1[3] + mB.y);
        }
        __syncthreads();
    }

    // reduce across the 4 lanes of each row-quad, write partials
#pragma unroll
    for (int mt = 0; mt < 2; mt++)
#pragma unroll
        for (int r = 0; r < 2; r++) {
            float v = wmax[mt][r];
            v = fmaxf(v, __shfl_xor_sync(0xFFFFFFFFu, v, 1));
            v = fmaxf(v, __shfl_xor_sync(0xFFFFFFFFu, v, 2));
            if (ctid == 0)
                d_embpart[blockIdx.y][bs][w * 32 + mt * 16 + r * 8 + g] = v;
        }
}

// =============================================================================
// Kernel 2: emb = relu(max over partials + b2); xg = emb . Wi + bi + bh
// (bwd direction stored time-reversed)
// =============================================================================
__global__ __launch_bounds__(128) void k2_inputgates(
    const float* __restrict__ b2,
    const float* __restrict__ Wi_f, const float* __restrict__ bi_f, const float* __restrict__ bh_f,
    const float* __restrict__ Wi_b, const float* __restrict__ bi_b, const float* __restrict__ bh_b)
{
    __shared__ float embs[128];
    const int tid = threadIdx.x;
    const int bs = blockIdx.x;
    const int b = bs / Sn, s = bs % Sn;

    float m = d_embpart[0][bs][tid];
#pragma unroll
    for (int r = 1; r < PSPLIT; r++) m = fmaxf(m, d_embpart[r][bs][tid]);
    embs[tid] = fmaxf(m + b2[tid], 0.f);   // deferred bias + relu (empty set -> 0)
    __syncthreads();

#pragma unroll
    for (int dir = 0; dir < 2; dir++) {
        const float* Wi = dir ? Wi_b : Wi_f;
        const float* bi = dir ? bi_b : bi_f;
        const float* bh = dir ? bh_b : bh_f;
        const int t = dir ? (Sn - 1 - s) : s;
#pragma unroll
        for (int rr = 0; rr < 4; rr++) {
            int g = rr * 128 + tid;
            const float* wr = Wi + (size_t)g * 128;
            float a = bi[g] + bh[g];
#pragma unroll 8
            for (int k = 0; k < 128; k += 4) {
                float4 w = *(const float4*)(wr + k);
                a = fmaf(w.x, embs[k], a);
                a = fmaf(w.y, embs[k + 1], a);
                a = fmaf(w.z, embs[k + 2], a);
                a = fmaf(w.w, embs[k + 3], a);
            }
            d_xg[dir][b][t][g] = a;
        }
    }
}

// =============================================================================
// Kernel 3: LSTM scan, cluster of 4 CTAs per direction, ONE cluster sync/step.
// Every rank multicasts its activated gates to all ranks (parity-buffered);
// each rank redundantly runs the c/h update and keeps h fully local.
// gact layout: [parity 2][gate 4][batch 4][unit 128]
// =============================================================================
#define K3_SMEM_FLOATS (16896 + 512 + 4096)
#define K3_SMEM_BYTES (K3_SMEM_FLOATS * 4)   // 86016

__global__ void __cluster_dims__(4, 1, 1) __launch_bounds__(128, 1)
k3_lstm(const float* __restrict__ Wh_f, const float* __restrict__ Wh_b)
{
    extern __shared__ float sm3[];
    float* Whs  = sm3;            // [128][132]
    float* hbuf = sm3 + 16896;    // [4][128] — local h, identical on all ranks
    float* gact = sm3 + 17408;    // [2][4][4][128]

    const int t = threadIdx.x;
    const int rank = blockIdx.x & 3;
    const int dir  = blockIdx.x >> 2;
    const float* Wh = dir ? Wh_b : Wh_f;

    const int R = rank * 128 + t;
    const float* wr = Wh + (size_t)R * 128;
#pragma unroll 8
    for (int k = 0; k < 128; k += 4)
        *(float4*)(Whs + t * 132 + k) = *(const float4*)(wr + k);
    for (int i = t; i < 512; i += 128) hbuf[i] = 0.f;

    float c[Bn];
#pragma unroll
    for (int b = 0; b < Bn; b++) c[b] = 0.f;

    // remote base address of my gate slot (par=0, gate=rank, b=0, unit=t) on each rank
    uint32_t rem[4];
#pragma unroll
    for (int r = 0; r < 4; r++)
        rem[r] = mapa_rank_(smem_u32_(&gact[rank * 512 + t]), (uint32_t)r);
    // byte offsets: parity stride 8192, batch stride 512

    const uint64_t* wp = (const uint64_t*)(Whs + t * 132);

    __syncthreads();
    cluster_sync_();

    int par = 0;
    for (int st = 0; st < Sn; ++st) {
        float xin[Bn];
#pragma unroll
        for (int b = 0; b < Bn; b++) xin[b] = d_xg[dir][b][st][R];

        uint64_t acc2[Bn];
#pragma unroll
        for (int b = 0; b < Bn; b++) acc2[b] = 0ull;
#pragma unroll 8
        for (int k2 = 0; k2 < 64; k2++) {
            uint64_t wv = wp[k2];
#pragma unroll
            for (int b = 0; b < Bn; b++) {
                uint64_t hv = *(const uint64_t*)(hbuf + b * 128 + k2 * 2);
                fma2_(acc2[b], wv, hv);
            }
        }

        // activate my gate slice, multicast to all 4 ranks (parity buffer)
#pragma unroll
        for (int b = 0; b < Bn; b++) {
            float lo = __uint_as_float((uint32_t)acc2[b]);
            float hi = __uint_as_float((uint32_t)(acc2[b] >> 32));
            float gv = lo + hi + xin[b];
            float av = (rank == 2) ? tanhf(gv) : sigmoid_(gv);
            uint32_t off = (uint32_t)(par * 8192 + b * 512);
#pragma unroll
            for (int r = 0; r < 4; r++) stc_f32_(rem[r] + off, av);
        }
        cluster_sync_();

        // redundant local c/h update from the 4 gate slices
        const float* gp = gact + par * 2048;
#pragma unroll
        for (int b = 0; b < Bn; b++) {
            float iv = gp[(0 * 4 + b) * 128 + t];
            float fv = gp[(1 * 4 + b) * 128 + t];
            float gg = gp[(2 * 4 + b) * 128 + t];
            float ov = gp[(3 * 4 + b) * 128 + t];
            float cn = fmaf(fv, c[b], iv * gg);
            c[b] = cn;
            hbuf[b * 128 + t] = ov * tanhf(cn);
        }
        __syncthreads();
        par ^= 1;
    }

    if (rank == 0) {
#pragma unroll
        for (int b = 0; b < Bn; b++) d_hfinal[dir][b][t] = hbuf[b * 128 + t];
    }
}

// =============================================================================
// Kernel 4: head — grid=4 (batch), 512 threads (thread = quarter W3 row).
// =============================================================================
__global__ __launch_bounds__(512) void k4_head(
    const float* __restrict__ W3, const float* __restrict__ b3,
    const float* __restrict__ W4, const float* __restrict__ b4,
    float* __restrict__ out)
{
    __shared__ float sf[256];
    __shared__ float red[128];
    const int tid = threadIdx.x;
    const int b = blockIdx.x;

    if (tid < 128) {
        sf[tid]       = d_hfinal[0][b][tid];
        sf[128 + tid] = d_hfinal[1][b][tid];
    }
    __syncthreads();

    const int r = tid >> 2, q = tid & 3;
    const float* w3r = W3 + (size_t)r * 256 + q * 64;
    const float* xf = sf + q * 64;

    float a = 0.f;
#pragma unroll 8
    for (int k = 0; k < 64; k += 4) {
        float4 wv = *(const float4*)(w3r + k);
        a = fmaf(wv.x, xf[k], a);
        a = fmaf(wv.y, xf[k + 1], a);
        a = fmaf(wv.z, xf[k + 2], a);
        a = fmaf(wv.w, xf[k + 3], a);
    }
    a += __shfl_xor_sync(0xFFFFFFFFu, a, 1);
    a += __shfl_xor_sync(0xFFFFFFFFu, a, 2);
    if (q == 0) red[r] = fmaxf(a + b3[r], 0.f) * W4[r];
    __syncthreads();
    for (int off = 64; off > 0; off >>= 1) {
        if (tid < off) red[tid] += red[tid + off];
        __syncthreads();
    }
    if (tid == 0) out[b] = red[0] + b4[0];
}

// =============================================================================
extern "C" void kernel_launch(void* const* d_in, const int* in_sizes, int n_in,
                              void* d_out, int out_size)
{
    const float* slices = (const float*)d_in[0];
    const float* pmask  = (const float*)d_in[1];
    const float* W1   = (const float*)d_in[2];
    const float* b1   = (const float*)d_in[3];
    const float* W2   = (const float*)d_in[4];
    const float* b2   = (const float*)d_in[5];
    const float* Wi_f = (const float*)d_in[6];
    const float* Wh_f = (const float*)d_in[7];
    const float* bi_f = (const float*)d_in[8];
    const float* bh_f = (const float*)d_in[9];
    const float* Wi_b = (const float*)d_in[10];
    const float* Wh_b = (const float*)d_in[11];
    const float* bi_b = (const float*)d_in[12];
    const float* bh_b = (const float*)d_in[13];
    const float* W3   = (const float*)d_in[14];
    const float* b3   = (const float*)d_in[15];
    const float* W4   = (const float*)d_in[16];
    const float* b4   = (const float*)d_in[17];
    float* out = (float*)d_out;

    cudaFuncSetAttribute(k3_lstm, cudaFuncAttributeMaxDynamicSharedMemorySize, K3_SMEM_BYTES);

    k1_mma<<<dim3(Bn * Sn, PSPLIT), 128>>>(slices, pmask, W1, b1, W2);
    k2_inputgates<<<Bn * Sn, 128>>>(b2, Wi_f, bi_f, bh_f, Wi_b, bi_b, bh_b);
    k3_lstm<<<8, 128, K3_SMEM_BYTES>>>(Wh_f, Wh_b);
    k4_head<<<4, 512>>>(W3, b3, W4, b4, out);
}

// round 11
// speedup vs baseline: 1.2182x; 1.2182x over previous
#include <cuda_runtime.h>
#include <cuda_fp16.h>
#include <cstdint>

#define Bn 4
#define Sn 80
#define Pn 6500
#define Hdim 128
#define PSPLIT 4
#define PCHUNK 1625   // 6500 / 4
#define NT1 13        // ceil(1625/128)
#define RS 35         // SMEM row stride in 32-bit words — conflict-free

// ---------------- scratch ----------------
__device__ float d_embpart[PSPLIT][Bn * Sn][128];
__device__ float d_xg[2][Bn][Sn][4 * Hdim];
__device__ float d_hfinal[2][Bn][Hdim];

// ---------------- helpers ----------------
__device__ __forceinline__ uint32_t smem_u32_(const void* p) {
    return (uint32_t)__cvta_generic_to_shared(p);
}
__device__ __forceinline__ uint32_t mapa_rank_(uint32_t a, uint32_t r) {
    uint32_t d;
    asm("mapa.shared::cluster.u32 %0, %1, %2;" : "=r"(d) : "r"(a), "r"(r));
    return d;
}
__device__ __forceinline__ void stc_f32_(uint32_t a, float v) {
    asm volatile("st.shared::cluster.f32 [%0], %1;" :: "r"(a), "f"(v) : "memory");
}
__device__ __forceinline__ void cluster_sync_() {
    asm volatile("barrier.cluster.arrive.aligned;" ::: "memory");
    asm volatile("barrier.cluster.wait.aligned;" ::: "memory");
}
__device__ __forceinline__ float sigmoid_(float x) { return 1.0f / (1.0f + expf(-x)); }

// pack two fp32 -> f16x2 word (v0 in low half)
__device__ __forceinline__ uint32_t packh2_(float v0, float v1) {
    __half2 h = __floats2half2_rn(v0, v1);
    return *reinterpret_cast<uint32_t*>(&h);
}

// m16n8k16 fp16 MMA, fp32 accumulate in-place
#define MMA_(c, a, b0v, b1v) \
    asm volatile("mma.sync.aligned.m16n8k16.row.col.f32.f16.f16.f32 " \
        "{%0,%1,%2,%3}, {%4,%5,%6,%7}, {%8,%9}, {%0,%1,%2,%3};" \
        : "+f"((c)[0]), "+f"((c)[1]), "+f"((c)[2]), "+f"((c)[3]) \
        : "r"((a)[0]), "r"((a)[1]), "r"((a)[2]), "r"((a)[3]), "r"(b0v), "r"(b1v))

// packed f32x2 fma (Blackwell)
__device__ __forceinline__ void fma2_(uint64_t& acc, uint64_t a, uint64_t b) {
    asm("fma.rn.f32x2 %0, %1, %2, %0;" : "+l"(acc) : "l"(a), "l"(b));
}

// =============================================================================
// Kernel 1: per-point MLP (2->64->128) + masked max, single-pass fp16 HMMA,
// double-buffered. grid (B*S, PSPLIT), 128 threads (4 warps).
// Warp w owns feature rows [w*32, w*32+32). D[feature][point] = W2 @ h^T, K=64.
// (Exact round-6 proven configuration.)
// =============================================================================
__global__ __launch_bounds__(128) void k1_mma(
    const float* __restrict__ slices, const float* __restrict__ pmask,
    const float* __restrict__ W1, const float* __restrict__ b1,
    const float* __restrict__ W2, const float* __restrict__ b2)
{
    __shared__ uint32_t Bf[2][128 * RS];   // f16x2 point tiles (buf0 also W2 staging)
    __shared__ float mskS[2][128];
    __shared__ float w1x[64], w1y[64], b1s[64];

    const int tid  = threadIdx.x;
    const int lane = tid & 31, w = tid >> 5;
    const int g = lane >> 2, ctid = lane & 3;
    const int bs = blockIdx.x;

    if (tid < 64) { w1x[tid] = W1[2 * tid]; w1y[tid] = W1[2 * tid + 1]; b1s[tid] = b1[tid]; }

    // ---- stage W2 fp16 into buffer 0 (scratch) ----
    {
        const float* wr = W2 + (size_t)tid * 64;
#pragma unroll 8
        for (int k = 0; k < 64; k += 2)
            Bf[0][tid * RS + (k >> 1)] = packh2_(wr[k], wr[k + 1]);
    }
    __syncthreads();

    // ---- A fragments (W2 fp16) into registers: [mtile][kstep][4] ----
    uint32_t Ah[2][4][4];
    float b2r[2][2];
#pragma unroll
    for (int mt = 0; mt < 2; mt++) {
        int rA = w * 32 + mt * 16 + g;
        b2r[mt][0] = b2[rA];
        b2r[mt][1] = b2[rA + 8];
#pragma unroll
        for (int ks = 0; ks < 4; ks++) {
            int base = rA * RS + ks * 8 + ctid;
            Ah[mt][ks][0] = Bf[0][base];
            Ah[mt][ks][1] = Bf[0][base + 8 * RS];
            Ah[mt][ks][2] = Bf[0][base + 4];
            Ah[mt][ks][3] = Bf[0][base + 8 * RS + 4];
        }
    }
    __syncthreads();   // staging done; buffers become point tiles

    const float* sp = slices + (size_t)bs * Pn * 2;
    const float* mp = pmask + (size_t)bs * Pn;
    const int pbeg = blockIdx.y * PCHUNK;
    const int pend = pbeg + PCHUNK;

    // producer: layer-1 + fp16 pack for one 128-pt tile into buffer buf
    auto produce = [&](int tile, int buf) {
        const int p = pbeg + tile * 128 + tid;
        float x = 0.f, y = 0.f, m = 0.f;
        if (p < pend) {
            float2 xy = *(const float2*)(sp + 2 * p);
            x = xy.x; y = xy.y; m = mp[p];
        }
        mskS[buf][tid] = m;
        uint32_t* br = &Bf[buf][tid * RS];
#pragma unroll 8
        for (int k = 0; k < 64; k += 2) {
            float v0 = fmaxf(fmaf(w1x[k],     x, fmaf(w1y[k],     y, b1s[k])),     0.f);
            float v1 = fmaxf(fmaf(w1x[k + 1], x, fmaf(w1y[k + 1], y, b1s[k + 1])), 0.f);
            br[k >> 1] = packh2_(v0, v1);
        }
    };

    float wmax[2][2] = {{0.f, 0.f}, {0.f, 0.f}};

    produce(0, 0);
    __syncthreads();

    for (int tile = 0; tile < NT1; ++tile) {
        const int cur = tile & 1, nxt = cur ^ 1;
        if (tile + 1 < NT1) produce(tile + 1, nxt);

        const uint32_t* Bp = Bf[cur];
        const float* msk = mskS[cur];

        // two point-blocks per iteration -> 4 independent accumulator chains
#pragma unroll 2
        for (int nbp = 0; nbp < 8; ++nbp) {
            float cA0[4] = {0.f, 0.f, 0.f, 0.f};
            float cA1[4] = {0.f, 0.f, 0.f, 0.f};
            float cB0[4] = {0.f, 0.f, 0.f, 0.f};
            float cB1[4] = {0.f, 0.f, 0.f, 0.f};
            const int nrA = nbp * 16 + g;
            const int nrB = nrA + 8;
#pragma unroll
            for (int ks = 0; ks < 4; ++ks) {
                int ia = nrA * RS + ks * 8 + ctid;
                int ib = nrB * RS + ks * 8 + ctid;
                uint32_t a0 = Bp[ia], a1 = Bp[ia + 4];
                uint32_t b0 = Bp[ib], b1 = Bp[ib + 4];
                MMA_(cA0, Ah[0][ks], a0, a1);
                MMA_(cB0, Ah[0][ks], b0, b1);
                MMA_(cA1, Ah[1][ks], a0, a1);
                MMA_(cB1, Ah[1][ks], b0, b1);
            }
            float2 mA = *(const float2*)&msk[nbp * 16 + ctid * 2];
            float2 mB = *(const float2*)&msk[nbp * 16 + 8 + ctid * 2];
            wmax[0][0] = fmaxf(wmax[0][0], fmaxf(cA0[0] + b2r[0][0], 0.f) * mA.x);
            wmax[0][0] = fmaxf(wmax[0][0], fmaxf(cA0[1] + b2r[0][0], 0.f) * mA.y);
            wmax[0][1] = fmaxf(wmax[0][1], fmaxf(cA0[2] + b2r[0][1], 0.f) * mA.x);
            wmax[0][1] = fmaxf(wmax[0][1], fmaxf(cA0[3] + b2r[0][1], 0.f) * mA.y);
            wmax[1][0] = fmaxf(wmax[1][0], fmaxf(cA1[0] + b2r[1][0], 0.f) * mA.x);
            wmax[1][0] = fmaxf(wmax[1][0], fmaxf(cA1[1] + b2r[1][0], 0.f) * mA.y);
            wmax[1][1] = fmaxf(wmax[1][1], fmaxf(cA1[2] + b2r[1][1], 0.f) * mA.x);
            wmax[1][1] = fmaxf(wmax[1][1], fmaxf(cA1[3] + b2r[1][1], 0.f) * mA.y);
            wmax[0][0] = fmaxf(wmax[0][0], fmaxf(cB0[0] + b2r[0][0], 0.f) * mB.x);
            wmax[0][0] = fmaxf(wmax[0][0], fmaxf(cB0[1] + b2r[0][0], 0.f) * mB.y);
            wmax[0][1] = fmaxf(wmax[0][1], fmaxf(cB0[2] + b2r[0][1], 0.f) * mB.x);
            wmax[0][1] = fmaxf(wmax[0][1], fmaxf(cB0[3] + b2r[0][1], 0.f) * mB.y);
            wmax[1][0] = fmaxf(wmax[1][0], fmaxf(cB1[0] + b2r[1][0], 0.f) * mB.x);
            wmax[1][0] = fmaxf(wmax[1][0], fmaxf(cB1[1] + b2r[1][0], 0.f) * mB.y);
            wmax[1][1] = fmaxf(wmax[1][1], fmaxf(cB1[2] + b2r[1][1], 0.f) * mB.x);
            wmax[1][1] = fmaxf(wmax[1][1], fmaxf(cB1[3] + b2r[1][1], 0.f) * mB.y);
        }
        __syncthreads();
    }

    // reduce across the 4 lanes of each row-quad, write partials
#pragma unroll
    for (int mt = 0; mt < 2; mt++)
#pragma unroll
        for (int r = 0; r < 2; r++) {
            float v = wmax[mt][r];
            v = fmaxf(v, __shfl_xor_sync(0xFFFFFFFFu, v, 1));
            v = fmaxf(v, __shfl_xor_sync(0xFFFFFFFFu, v, 2));
            if (ctid == 0)
                d_embpart[blockIdx.y][bs][w * 32 + mt * 16 + r * 8 + g] = v;
        }
}

// =============================================================================
// Kernel 2: emb = max over partials; xg = emb . Wi + bi + bh (bwd time-reversed)
// =============================================================================
__global__ __launch_bounds__(128) void k2_inputgates(
    const float* __restrict__ Wi_f, const float* __restrict__ bi_f, const float* __restrict__ bh_f,
    const float* __restrict__ Wi_b, const float* __restrict__ bi_b, const float* __restrict__ bh_b)
{
    __shared__ float embs[128];
    const int tid = threadIdx.x;
    const int bs = blockIdx.x;
    const int b = bs / Sn, s = bs % Sn;

    float m = d_embpart[0][bs][tid];
    m = fmaxf(m, d_embpart[1][bs][tid]);
    m = fmaxf(m, d_embpart[2][bs][tid]);
    m = fmaxf(m, d_embpart[3][bs][tid]);
    embs[tid] = m;
    __syncthreads();

#pragma unroll
    for (int dir = 0; dir < 2; dir++) {
        const float* Wi = dir ? Wi_b : Wi_f;
        const float* bi = dir ? bi_b : bi_f;
        const float* bh = dir ? bh_b : bh_f;
        const int t = dir ? (Sn - 1 - s) : s;
#pragma unroll
        for (int rr = 0; rr < 4; rr++) {
            int g = rr * 128 + tid;
            const float* wr = Wi + (size_t)g * 128;
            float a = bi[g] + bh[g];
#pragma unroll 8
            for (int k = 0; k < 128; k += 4) {
                float4 w = *(const float4*)(wr + k);
                a = fmaf(w.x, embs[k], a);
                a = fmaf(w.y, embs[k + 1], a);
                a = fmaf(w.z, embs[k + 2], a);
                a = fmaf(w.w, embs[k + 3], a);
            }
            d_xg[dir][b][t][g] = a;
        }
    }
}

// =============================================================================
// Kernel 3: LSTM scan, cluster of 4 CTAs per direction. Wh rows live in
// REGISTERS (64 x f32x2 per thread); step loop does only broadcast hbuf LDS
// + fma2. Two-sync protocol identical to the proven round-6 version.
// =============================================================================
__global__ void __cluster_dims__(4, 1, 1) __launch_bounds__(128, 1)
k3_lstm(const float* __restrict__ Wh_f, const float* __restrict__ Wh_b)
{
    __shared__ __align__(16) float hbuf[Bn * 128];        // h, written by rank 0
    __shared__ __align__(16) float gact[4 * Bn * 128];    // gate slices (rank 0)

    const int t = threadIdx.x;
    const int rank = blockIdx.x & 3;
    const int dir  = blockIdx.x >> 2;
    const float* Wh = dir ? Wh_b : Wh_f;
    const int R = rank * 128 + t;

    // ---- weights into registers: 128 floats = 64 packed f32x2 ----
    uint64_t wreg[64];
    {
        const uint64_t* wr = (const uint64_t*)(Wh + (size_t)R * 128);
#pragma unroll
        for (int i = 0; i < 64; i++) wreg[i] = wr[i];
    }

    for (int i = t; i < Bn * 128; i += 128) hbuf[i] = 0.f;

    float c[Bn];
#pragma unroll
    for (int b = 0; b < Bn; b++) c[b] = 0.f;

    uint32_t ga_rem[Bn];
#pragma unroll
    for (int b = 0; b < Bn; b++)
        ga_rem[b] = mapa_rank_(smem_u32_(&gact[(rank * Bn + b) * 128 + t]), 0);
    uint32_t hb_rem[4][Bn];
#pragma unroll
    for (int r = 0; r < 4; r++)
#pragma unroll
        for (int b = 0; b < Bn; b++)
            hb_rem[r][b] = mapa_rank_(smem_u32_(&hbuf[b * 128 + t]), (uint32_t)r);

    __syncthreads();
    cluster_sync_();

    for (int st = 0; st < Sn; ++st) {
        float xin[Bn];
#pragma unroll
        for (int b = 0; b < Bn; b++) xin[b] = d_xg[dir][b][st][R];

        uint64_t acc2[Bn];
#pragma unroll
        for (int b = 0; b < Bn; b++) acc2[b] = 0ull;
#pragma unroll
        for (int k2 = 0; k2 < 64; k2++) {
            const uint64_t wv = wreg[k2];
#pragma unroll
            for (int b = 0; b < Bn; b++) {
                uint64_t hv = *(const uint64_t*)(hbuf + b * 128 + k2 * 2);
                fma2_(acc2[b], wv, hv);
            }
        }

#pragma unroll
        for (int b = 0; b < Bn; b++) {
            float lo = __uint_as_float((uint32_t)acc2[b]);
            float hi = __uint_as_float((uint32_t)(acc2[b] >> 32));
            float gv = lo + hi + xin[b];
            float av = (rank == 2) ? tanhf(gv) : sigmoid_(gv);
            stc_f32_(ga_rem[b], av);
        }
        cluster_sync_();

        if (rank == 0) {
#pragma unroll
            for (int b = 0; b < Bn; b++) {
                float iv = gact[(0 * Bn + b) * 128 + t];
                float fv = gact[(1 * Bn + b) * 128 + t];
                float gg = gact[(2 * Bn + b) * 128 + t];
                float ov = gact[(3 * Bn + b) * 128 + t];
                float cn = fmaf(fv, c[b], iv * gg);
                c[b] = cn;
                float hv = ov * tanhf(cn);
#pragma unroll
                for (int r = 0; r < 4; r++) stc_f32_(hb_rem[r][b], hv);
            }
        }
        cluster_sync_();
    }

    if (rank == 0) {
#pragma unroll
        for (int b = 0; b < Bn; b++) d_hfinal[dir][b][t] = hbuf[b * 128 + t];
    }
}

// =============================================================================
// Kernel 4: head — grid=4 (batch), 512 threads (thread = quarter W3 row).
// =============================================================================
__global__ __launch_bounds__(512) void k4_head(
    const float* __restrict__ W3, const float* __restrict__ b3,
    const float* __restrict__ W4, const float* __restrict__ b4,
    float* __restrict__ out)
{
    __shared__ float sf[256];
    __shared__ float red[128];
    const int tid = threadIdx.x;
    const int b = blockIdx.x;

    if (tid < 128) {
        sf[tid]       = d_hfinal[0][b][tid];
        sf[128 + tid] = d_hfinal[1][b][tid];
    }
    __syncthreads();

    const int r = tid >> 2, q = tid & 3;
    const float* w3r = W3 + (size_t)r * 256 + q * 64;
    const float* xf = sf + q * 64;

    float a = 0.f;
#pragma unroll 8
    for (int k = 0; k < 64; k += 4) {
        float4 wv = *(const float4*)(w3r + k);
        a = fmaf(wv.x, xf[k], a);
        a = fmaf(wv.y, xf[k + 1], a);
        a = fmaf(wv.z, xf[k + 2], a);
        a = fmaf(wv.w, xf[k + 3], a);
    }
    a += __shfl_xor_sync(0xFFFFFFFFu, a, 1);
    a += __shfl_xor_sync(0xFFFFFFFFu, a, 2);
    if (q == 0) red[r] = fmaxf(a + b3[r], 0.f) * W4[r];
    __syncthreads();
    for (int off = 64; off > 0; off >>= 1) {
        if (tid < off) red[tid] += red[tid + off];
        __syncthreads();
    }
    if (tid == 0) out[b] = red[0] + b4[0];
}

// =============================================================================
extern "C" void kernel_launch(void* const* d_in, const int* in_sizes, int n_in,
                              void* d_out, int out_size)
{
    const float* slices = (const float*)d_in[0];
    const float* pmask  = (const float*)d_in[1];
    const float* W1   = (const float*)d_in[2];
    const float* b1   = (const float*)d_in[3];
    const float* W2   = (const float*)d_in[4];
    const float* b2   = (const float*)d_in[5];
    const float* Wi_f = (const float*)d_in[6];
    const float* Wh_f = (const float*)d_in[7];
    const float* bi_f = (const float*)d_in[8];
    const float* bh_f = (const float*)d_in[9];
    const float* Wi_b = (const float*)d_in[10];
    const float* Wh_b = (const float*)d_in[11];
    const float* bi_b = (const float*)d_in[12];
    const float* bh_b = (const float*)d_in[13];
    const float* W3   = (const float*)d_in[14];
    const float* b3   = (const float*)d_in[15];
    const float* W4   = (const float*)d_in[16];
    const float* b4   = (const float*)d_in[17];
    float* out = (float*)d_out;

    k1_mma<<<dim3(Bn * Sn, PSPLIT), 128>>>(slices, pmask, W1, b1, W2, b2);
    k2_inputgates<<<Bn * Sn, 128>>>(Wi_f, bi_f, bh_f, Wi_b, bi_b, bh_b);
    k3_lstm<<<8, 128>>>(Wh_f, Wh_b);
    k4_head<<<4, 512>>>(W3, b3, W4, b4, out);
}

// round 13
// speedup vs baseline: 1.3316x; 1.0930x over previous
#include <cuda_runtime.h>
#include <cuda_fp16.h>
#include <cstdint>

#define Bn 4
#define Sn 80
#define Pn 6500
#define Hdim 128
#define PSPLIT 4
#define PCHUNK 1625   // 6500 / 4
#define NT1 13        // ceil(1625/128)
#define RS 35         // SMEM row stride in 32-bit words — conflict-free

// ---------------- scratch ----------------
__device__ float d_embpart[PSPLIT][Bn * Sn][128];
__device__ float d_xg[2][Bn][Sn][4 * Hdim];
__device__ float d_hfinal[2][Bn][Hdim];

// ---------------- helpers ----------------
__device__ __forceinline__ uint32_t smem_u32_(const void* p) {
    return (uint32_t)__cvta_generic_to_shared(p);
}
__device__ __forceinline__ uint32_t mapa_rank_(uint32_t a, uint32_t r) {
    uint32_t d;
    asm("mapa.shared::cluster.u32 %0, %1, %2;" : "=r"(d) : "r"(a), "r"(r));
    return d;
}
__device__ __forceinline__ void stc_f32_(uint32_t a, float v) {
    asm volatile("st.shared::cluster.f32 [%0], %1;" :: "r"(a), "f"(v) : "memory");
}
__device__ __forceinline__ void cluster_sync_() {
    asm volatile("barrier.cluster.arrive.aligned;" ::: "memory");
    asm volatile("barrier.cluster.wait.aligned;" ::: "memory");
}
__device__ __forceinline__ float sigmoid_(float x) { return 1.0f / (1.0f + expf(-x)); }

// pack two fp32 -> f16x2 word (v0 in low half)
__device__ __forceinline__ uint32_t packh2_(float v0, float v1) {
    __half2 h = __floats2half2_rn(v0, v1);
    return *reinterpret_cast<uint32_t*>(&h);
}

// m16n8k16 fp16 MMA, fp32 accumulate in-place
#define MMA_(c, a, b0v, b1v) \
    asm volatile("mma.sync.aligned.m16n8k16.row.col.f32.f16.f16.f32 " \
        "{%0,%1,%2,%3}, {%4,%5,%6,%7}, {%8,%9}, {%0,%1,%2,%3};" \
        : "+f"((c)[0]), "+f"((c)[1]), "+f"((c)[2]), "+f"((c)[3]) \
        : "r"((a)[0]), "r"((a)[1]), "r"((a)[2]), "r"((a)[3]), "r"(b0v), "r"(b1v))

// packed f32x2 fma (Blackwell)
__device__ __forceinline__ void fma2_(uint64_t& acc, uint64_t a, uint64_t b) {
    asm("fma.rn.f32x2 %0, %1, %2, %0;" : "+l"(acc) : "l"(a), "l"(b));
}

// =============================================================================
// Kernel 1: per-point MLP (2->64->128) + masked max, single-pass fp16 HMMA,
// double-buffered. grid (B*S, PSPLIT), 128 threads (4 warps).
// (Exact round-6/11 proven configuration — untouched.)
// =============================================================================
__global__ __launch_bounds__(128) void k1_mma(
    const float* __restrict__ slices, const float* __restrict__ pmask,
    const float* __restrict__ W1, const float* __restrict__ b1,
    const float* __restrict__ W2, const float* __restrict__ b2)
{
    __shared__ uint32_t Bf[2][128 * RS];   // f16x2 point tiles (buf0 also W2 staging)
    __shared__ float mskS[2][128];
    __shared__ float w1x[64], w1y[64], b1s[64];

    const int tid  = threadIdx.x;
    const int lane = tid & 31, w = tid >> 5;
    const int g = lane >> 2, ctid = lane & 3;
    const int bs = blockIdx.x;

    if (tid < 64) { w1x[tid] = W1[2 * tid]; w1y[tid] = W1[2 * tid + 1]; b1s[tid] = b1[tid]; }

    {
        const float* wr = W2 + (size_t)tid * 64;
#pragma unroll 8
        for (int k = 0; k < 64; k += 2)
            Bf[0][tid * RS + (k >> 1)] = packh2_(wr[k], wr[k + 1]);
    }
    __syncthreads();

    uint32_t Ah[2][4][4];
    float b2r[2][2];
#pragma unroll
    for (int mt = 0; mt < 2; mt++) {
        int rA = w * 32 + mt * 16 + g;
        b2r[mt][0] = b2[rA];
        b2r[mt][1] = b2[rA + 8];
#pragma unroll
        for (int ks = 0; ks < 4; ks++) {
            int base = rA * RS + ks * 8 + ctid;
            Ah[mt][ks][0] = Bf[0][base];
            Ah[mt][ks][1] = Bf[0][base + 8 * RS];
            Ah[mt][ks][2] = Bf[0][base + 4];
            Ah[mt][ks][3] = Bf[0][base + 8 * RS + 4];
        }
    }
    __syncthreads();

    const float* sp = slices + (size_t)bs * Pn * 2;
    const float* mp = pmask + (size_t)bs * Pn;
    const int pbeg = blockIdx.y * PCHUNK;
    const int pend = pbeg + PCHUNK;

    auto produce = [&](int tile, int buf) {
        const int p = pbeg + tile * 128 + tid;
        float x = 0.f, y = 0.f, m = 0.f;
        if (p < pend) {
            float2 xy = *(const float2*)(sp + 2 * p);
            x = xy.x; y = xy.y; m = mp[p];
        }
        mskS[buf][tid] = m;
        uint32_t* br = &Bf[buf][tid * RS];
#pragma unroll 8
        for (int k = 0; k < 64; k += 2) {
            float v0 = fmaxf(fmaf(w1x[k],     x, fmaf(w1y[k],     y, b1s[k])),     0.f);
            float v1 = fmaxf(fmaf(w1x[k + 1], x, fmaf(w1y[k + 1], y, b1s[k + 1])), 0.f);
            br[k >> 1] = packh2_(v0, v1);
        }
    };

    float wmax[2][2] = {{0.f, 0.f}, {0.f, 0.f}};

    produce(0, 0);
    __syncthreads();

    for (int tile = 0; tile < NT1; ++tile) {
        const int cur = tile & 1, nxt = cur ^ 1;
        if (tile + 1 < NT1) produce(tile + 1, nxt);

        const uint32_t* Bp = Bf[cur];
        const float* msk = mskS[cur];

#pragma unroll 2
        for (int nbp = 0; nbp < 8; ++nbp) {
            float cA0[4] = {0.f, 0.f, 0.f, 0.f};
            float cA1[4] = {0.f, 0.f, 0.f, 0.f};
            float cB0[4] = {0.f, 0.f, 0.f, 0.f};
            float cB1[4] = {0.f, 0.f, 0.f, 0.f};
            const int nrA = nbp * 16 + g;
            const int nrB = nrA + 8;
#pragma unroll
            for (int ks = 0; ks < 4; ++ks) {
                int ia = nrA * RS + ks * 8 + ctid;
                int ib = nrB * RS + ks * 8 + ctid;
                uint32_t a0 = Bp[ia], a1 = Bp[ia + 4];
                uint32_t b0 = Bp[ib], b1 = Bp[ib + 4];
                MMA_(cA0, Ah[0][ks], a0, a1);
                MMA_(cB0, Ah[0][ks], b0, b1);
                MMA_(cA1, Ah[1][ks], a0, a1);
                MMA_(cB1, Ah[1][ks], b0, b1);
            }
            float2 mA = *(const float2*)&msk[nbp * 16 + ctid * 2];
            float2 mB = *(const float2*)&msk[nbp * 16 + 8 + ctid * 2];
            wmax[0][0] = fmaxf(wmax[0][0], fmaxf(cA0[0] + b2r[0][0], 0.f) * mA.x);
            wmax[0][0] = fmaxf(wmax[0][0], fmaxf(cA0[1] + b2r[0][0], 0.f) * mA.y);
            wmax[0][1] = fmaxf(wmax[0][1], fmaxf(cA0[2] + b2r[0][1], 0.f) * mA.x);
            wmax[0][1] = fmaxf(wmax[0][1], fmaxf(cA0[3] + b2r[0][1], 0.f) * mA.y);
            wmax[1][0] = fmaxf(wmax[1][0], fmaxf(cA1[0] + b2r[1][0], 0.f) * mA.x);
            wmax[1][0] = fmaxf(wmax[1][0], fmaxf(cA1[1] + b2r[1][0], 0.f) * mA.y);
            wmax[1][1] = fmaxf(wmax[1][1], fmaxf(cA1[2] + b2r[1][1], 0.f) * mA.x);
            wmax[1][1] = fmaxf(wmax[1][1], fmaxf(cA1[3] + b2r[1][1], 0.f) * mA.y);
            wmax[0][0] = fmaxf(wmax[0][0], fmaxf(cB0[0] + b2r[0][0], 0.f) * mB.x);
            wmax[0][0] = fmaxf(wmax[0][0], fmaxf(cB0[1] + b2r[0][0], 0.f) * mB.y);
            wmax[0][1] = fmaxf(wmax[0][1], fmaxf(cB0[2] + b2r[0][1], 0.f) * mB.x);
            wmax[0][1] = fmaxf(wmax[0][1], fmaxf(cB0[3] + b2r[0][1], 0.f) * mB.y);
            wmax[1][0] = fmaxf(wmax[1][0], fmaxf(cB1[0] + b2r[1][0], 0.f) * mB.x);
            wmax[1][0] = fmaxf(wmax[1][0], fmaxf(cB1[1] + b2r[1][0], 0.f) * mB.y);
            wmax[1][1] = fmaxf(wmax[1][1], fmaxf(cB1[2] + b2r[1][1], 0.f) * mB.x);
            wmax[1][1] = fmaxf(wmax[1][1], fmaxf(cB1[3] + b2r[1][1], 0.f) * mB.y);
        }
        __syncthreads();
    }

#pragma unroll
    for (int mt = 0; mt < 2; mt++)
#pragma unroll
        for (int r = 0; r < 2; r++) {
            float v = wmax[mt][r];
            v = fmaxf(v, __shfl_xor_sync(0xFFFFFFFFu, v, 1));
            v = fmaxf(v, __shfl_xor_sync(0xFFFFFFFFu, v, 2));
            if (ctid == 0)
                d_embpart[blockIdx.y][bs][w * 32 + mt * 16 + r * 8 + g] = v;
        }
}

// =============================================================================
// Kernel 2: one block per s (grid=80); 4 batches share each Wi float4 in regs.
// Same k-ascending accumulation order as before -> identical math per gate.
// =============================================================================
__global__ __launch_bounds__(128) void k2_inputgates(
    const float* __restrict__ Wi_f, const float* __restrict__ bi_f, const float* __restrict__ bh_f,
    const float* __restrict__ Wi_b, const float* __restrict__ bi_b, const float* __restrict__ bh_b)
{
    __shared__ float embs[Bn][128];
    const int tid = threadIdx.x;
    const int s = blockIdx.x;

#pragma unroll
    for (int b = 0; b < Bn; b++) {
        const int bs = b * Sn + s;
        float m = d_embpart[0][bs][tid];
        m = fmaxf(m, d_embpart[1][bs][tid]);
        m = fmaxf(m, d_embpart[2][bs][tid]);
        m = fmaxf(m, d_embpart[3][bs][tid]);
        embs[b][tid] = m;
    }
    __syncthreads();

#pragma unroll
    for (int dir = 0; dir < 2; dir++) {
        const float* Wi = dir ? Wi_b : Wi_f;
        const float* bi = dir ? bi_b : bi_f;
        const float* bh = dir ? bh_b : bh_f;
        const int t = dir ? (Sn - 1 - s) : s;
#pragma unroll
        for (int rr = 0; rr < 4; rr++) {
            int g = rr * 128 + tid;
            const float* wr = Wi + (size_t)g * 128;
            float a0 = bi[g] + bh[g];
            float acc[Bn] = {a0, a0, a0, a0};
#pragma unroll 8
            for (int k = 0; k < 128; k += 4) {
                float4 w = *(const float4*)(wr + k);
#pragma unroll
                for (int b = 0; b < Bn; b++) {
                    acc[b] = fmaf(w.x, embs[b][k],     acc[b]);
                    acc[b] = fmaf(w.y, embs[b][k + 1], acc[b]);
                    acc[b] = fmaf(w.z, embs[b][k + 2], acc[b]);
                    acc[b] = fmaf(w.w, embs[b][k + 3], acc[b]);
                }
            }
#pragma unroll
            for (int b = 0; b < Bn; b++) d_xg[dir][b][t][g] = acc[b];
        }
    }
}

// =============================================================================
// Kernel 3: LSTM scan, cluster of 4 CTAs per direction. Wh in registers;
// SINGLE cluster sync per step: each rank multicasts its activated gate slice
// to all ranks (parity-buffered gact), then all ranks redundantly run the
// c/h update on a fully local hbuf. hbuf gemm uses LDS.128.
// gact layout: [parity 2][gate 4][batch 4][unit 128]
// =============================================================================
__global__ void __cluster_dims__(4, 1, 1) __launch_bounds__(128, 1)
k3_lstm(const float* __restrict__ Wh_f, const float* __restrict__ Wh_b)
{
    __shared__ __align__(16) float hbuf[Bn * 128];          // local h (all ranks identical)
    __shared__ __align__(16) float gact[2 * 4 * Bn * 128];  // parity-buffered gate slices

    const int t = threadIdx.x;
    const int rank = blockIdx.x & 3;
    const int dir  = blockIdx.x >> 2;
    const float* Wh = dir ? Wh_b : Wh_f;
    const int R = rank * 128 + t;

    // weights into registers: 128 floats = 64 packed f32x2
    uint64_t wreg[64];
    {
        const uint64_t* wr = (const uint64_t*)(Wh + (size_t)R * 128);
#pragma unroll
        for (int i = 0; i < 64; i++) wreg[i] = wr[i];
    }

    for (int i = t; i < Bn * 128; i += 128) hbuf[i] = 0.f;

    float c[Bn];
#pragma unroll
    for (int b = 0; b < Bn; b++) c[b] = 0.f;

    // remote addr of my gate slot (par=0, gate=rank, b=0, unit=t) on each rank;
    // per-write byte offset: par*8192 + b*512
    uint32_t rem[4];
#pragma unroll
    for (int r = 0; r < 4; r++)
        rem[r] = mapa_rank_(smem_u32_(&gact[rank * 512 + t]), (uint32_t)r);

    __syncthreads();
    cluster_sync_();

    int par = 0;
    for (int st = 0; st < Sn; ++st) {
        float xin[Bn];
#pragma unroll
        for (int b = 0; b < Bn; b++) xin[b] = d_xg[dir][b][st][R];

        uint64_t acc2[Bn];
#pragma unroll
        for (int b = 0; b < Bn; b++) acc2[b] = 0ull;
#pragma unroll
        for (int k4 = 0; k4 < 32; k4++) {
            const uint64_t w0 = wreg[2 * k4], w1 = wreg[2 * k4 + 1];
#pragma unroll
            for (int b = 0; b < Bn; b++) {
                longlong2 hv = *(const longlong2*)(hbuf + b * 128 + k4 * 4);  // LDS.128
                fma2_(acc2[b], w0, (uint64_t)hv.x);
                fma2_(acc2[b], w1, (uint64_t)hv.y);
            }
        }

        // activate my gate slice, multicast to all 4 ranks (parity buffer)
#pragma unroll
        for (int b = 0; b < Bn; b++) {
            float lo = __uint_as_float((uint32_t)acc2[b]);
            float hi = __uint_as_float((uint32_t)(acc2[b] >> 32));
            float gv = lo + hi + xin[b];
            float av = (rank == 2) ? tanhf(gv) : sigmoid_(gv);
            uint32_t off = (uint32_t)(par * 8192 + b * 512);
#pragma unroll
            for (int r = 0; r < 4; r++) stc_f32_(rem[r] + off, av);
        }
        cluster_sync_();

        // redundant local c/h update (every rank)
        const float* gp = gact + par * 2048;
#pragma unroll
        for (int b = 0; b < Bn; b++) {
            float iv = gp[0 * 512 + b * 128 + t];
            float fv = gp[1 * 512 + b * 128 + t];
            float gg = gp[2 * 512 + b * 128 + t];
            float ov = gp[3 * 512 + b * 128 + t];
            float cn = fmaf(fv, c[b], iv * gg);
            c[b] = cn;
            hbuf[b * 128 + t] = ov * tanhf(cn);
        }
        __syncthreads();
        par ^= 1;
    }

    if (rank == 0) {
#pragma unroll
        for (int b = 0; b < Bn; b++) d_hfinal[dir][b][t] = hbuf[b * 128 + t];
    }
}

// =============================================================================
// Kernel 4: head — grid=4 (batch), 512 threads (thread = quarter W3 row).
// =============================================================================
__global__ __launch_bounds__(512) void k4_head(
    const float* __restrict__ W3, const float* __restrict__ b3,
    const float* __restrict__ W4, const float* __restrict__ b4,
    float* __restrict__ out)
{
    __shared__ float sf[256];
    __shared__ float red[128];
    const int tid = threadIdx.x;
    const int b = blockIdx.x;

    if (tid < 128) {
        sf[tid]       = d_hfinal[0][b][tid];
        sf[128 + tid] = d_hfinal[1][b][tid];
    }
    __syncthreads();

    const int r = tid >> 2, q = tid & 3;
    const float* w3r = W3 + (size_t)r * 256 + q * 64;
    const float* xf = sf + q * 64;

    float a = 0.f;
#pragma unroll 8
    for (int k = 0; k < 64; k += 4) {
        float4 wv = *(const float4*)(w3r + k);
        a = fmaf(wv.x, xf[k], a);
        a = fmaf(wv.y, xf[k + 1], a);
        a = fmaf(wv.z, xf[k + 2], a);
        a = fmaf(wv.w, xf[k + 3], a);
    }
    a += __shfl_xor_sync(0xFFFFFFFFu, a, 1);
    a += __shfl_xor_sync(0xFFFFFFFFu, a, 2);
    if (q == 0) red[r] = fmaxf(a + b3[r], 0.f) * W4[r];
    __syncthreads();
    for (int off = 64; off > 0; off >>= 1) {
        if (tid < off) red[tid] += red[tid + off];
        __syncthreads();
    }
    if (tid == 0) out[b] = red[0] + b4[0];
}

// =============================================================================
extern "C" void kernel_launch(void* const* d_in, const int* in_sizes, int n_in,
                              void* d_out, int out_size)
{
    const float* slices = (const float*)d_in[0];
    const float* pmask  = (const float*)d_in[1];
    const float* W1   = (const float*)d_in[2];
    const float* b1   = (const float*)d_in[3];
    const float* W2   = (const float*)d_in[4];
    const float* b2   = (const float*)d_in[5];
    const float* Wi_f = (const float*)d_in[6];
    const float* Wh_f = (const float*)d_in[7];
    const float* bi_f = (const float*)d_in[8];
    const float* bh_f = (const float*)d_in[9];
    const float* Wi_b = (const float*)d_in[10];
    const float* Wh_b = (const float*)d_in[11];
    const float* bi_b = (const float*)d_in[12];
    const float* bh_b = (const float*)d_in[13];
    const float* W3   = (const float*)d_in[14];
    const float* b3   = (const float*)d_in[15];
    const float* W4   = (const float*)d_in[16];
    const float* b4   = (const float*)d_in[17];
    float* out = (float*)d_out;

    k1_mma<<<dim3(Bn * Sn, PSPLIT), 128>>>(slices, pmask, W1, b1, W2, b2);
    k2_inputgates<<<Sn, 128>>>(Wi_f, bi_f, bh_f, Wi_b, bi_b, bh_b);
    k3_lstm<<<8, 128>>>(Wh_f, Wh_b);
    k4_head<<<4, 512>>>(W3, b3, W4, b4, out);
}

// round 14
// speedup vs baseline: 1.3622x; 1.0230x over previous
#include <cuda_runtime.h>
#include <cuda_fp16.h>
#include <cstdint>

#define Bn 4
#define Sn 80
#define Pn 6500
#define Hdim 128
#define PSPLIT 4
#define PCHUNK 1625   // 6500 / 4
#define NT1 13        // ceil(1625/128)
#define RS 35         // SMEM row stride in 32-bit words — conflict-free
#define NEGBIG (-1.0e30f)

// ---------------- scratch ----------------
__device__ float d_embpart[PSPLIT][Bn * Sn][128];
__device__ float d_xg[2][Bn][Sn][4 * Hdim];
__device__ float d_hfinal[2][Bn][Hdim];

// ---------------- helpers ----------------
__device__ __forceinline__ uint32_t smem_u32_(const void* p) {
    return (uint32_t)__cvta_generic_to_shared(p);
}
__device__ __forceinline__ uint32_t mapa_rank_(uint32_t a, uint32_t r) {
    uint32_t d;
    asm("mapa.shared::cluster.u32 %0, %1, %2;" : "=r"(d) : "r"(a), "r"(r));
    return d;
}
__device__ __forceinline__ void stc_f32_(uint32_t a, float v) {
    asm volatile("st.shared::cluster.f32 [%0], %1;" :: "r"(a), "f"(v) : "memory");
}
__device__ __forceinline__ void cluster_sync_() {
    asm volatile("barrier.cluster.arrive.aligned;" ::: "memory");
    asm volatile("barrier.cluster.wait.aligned;" ::: "memory");
}
__device__ __forceinline__ float sigmoid_(float x) { return 1.0f / (1.0f + expf(-x)); }

// pack two fp32 -> f16x2 word (v0 in low half)
__device__ __forceinline__ uint32_t packh2_(float v0, float v1) {
    __half2 h = __floats2half2_rn(v0, v1);
    return *reinterpret_cast<uint32_t*>(&h);
}

// m16n8k16 fp16 MMA, fp32 accumulate in-place
#define MMA_(c, a, b0v, b1v) \
    asm volatile("mma.sync.aligned.m16n8k16.row.col.f32.f16.f16.f32 " \
        "{%0,%1,%2,%3}, {%4,%5,%6,%7}, {%8,%9}, {%0,%1,%2,%3};" \
        : "+f"((c)[0]), "+f"((c)[1]), "+f"((c)[2]), "+f"((c)[3]) \
        : "r"((a)[0]), "r"((a)[1]), "r"((a)[2]), "r"((a)[3]), "r"(b0v), "r"(b1v))

// packed f32x2 fma (Blackwell)
__device__ __forceinline__ void fma2_(uint64_t& acc, uint64_t a, uint64_t b) {
    asm("fma.rn.f32x2 %0, %1, %2, %0;" : "+l"(acc) : "l"(a), "l"(b));
}

// =============================================================================
// Kernel 1: per-point MLP (2->64->128) + masked max, single-pass fp16 HMMA,
// double-buffered. grid (B*S, PSPLIT), 128 threads (4 warps).
// DEFERRED epilogue: wmax = max(acc + maskadd); bias+relu applied in k2.
// (Bit-identical emb: relu/(+b2) are monotone, mask in {0,1}.)
// =============================================================================
__global__ __launch_bounds__(128) void k1_mma(
    const float* __restrict__ slices, const float* __restrict__ pmask,
    const float* __restrict__ W1, const float* __restrict__ b1,
    const float* __restrict__ W2)
{
    __shared__ uint32_t Bf[2][128 * RS];   // f16x2 point tiles (buf0 also W2 staging)
    __shared__ float mskS[2][128];         // maskadd: 0 or -1e30
    __shared__ float w1x[64], w1y[64], b1s[64];

    const int tid  = threadIdx.x;
    const int lane = tid & 31, w = tid >> 5;
    const int g = lane >> 2, ctid = lane & 3;
    const int bs = blockIdx.x;

    if (tid < 64) { w1x[tid] = W1[2 * tid]; w1y[tid] = W1[2 * tid + 1]; b1s[tid] = b1[tid]; }

    {
        const float* wr = W2 + (size_t)tid * 64;
#pragma unroll 8
        for (int k = 0; k < 64; k += 2)
            Bf[0][tid * RS + (k >> 1)] = packh2_(wr[k], wr[k + 1]);
    }
    __syncthreads();

    uint32_t Ah[2][4][4];
#pragma unroll
    for (int mt = 0; mt < 2; mt++) {
        int rA = w * 32 + mt * 16 + g;
#pragma unroll
        for (int ks = 0; ks < 4; ks++) {
            int base = rA * RS + ks * 8 + ctid;
            Ah[mt][ks][0] = Bf[0][base];
            Ah[mt][ks][1] = Bf[0][base + 8 * RS];
            Ah[mt][ks][2] = Bf[0][base + 4];
            Ah[mt][ks][3] = Bf[0][base + 8 * RS + 4];
        }
    }
    __syncthreads();

    const float* sp = slices + (size_t)bs * Pn * 2;
    const float* mp = pmask + (size_t)bs * Pn;
    const int pbeg = blockIdx.y * PCHUNK;
    const int pend = pbeg + PCHUNK;

    auto produce = [&](int tile, int buf) {
        const int p = pbeg + tile * 128 + tid;
        float x = 0.f, y = 0.f, ma = NEGBIG;
        if (p < pend) {
            float2 xy = *(const float2*)(sp + 2 * p);
            x = xy.x; y = xy.y;
            if (mp[p] > 0.f) ma = 0.f;
        }
        mskS[buf][tid] = ma;
        uint32_t* br = &Bf[buf][tid * RS];
#pragma unroll 8
        for (int k = 0; k < 64; k += 2) {
            float v0 = fmaxf(fmaf(w1x[k],     x, fmaf(w1y[k],     y, b1s[k])),     0.f);
            float v1 = fmaxf(fmaf(w1x[k + 1], x, fmaf(w1y[k + 1], y, b1s[k + 1])), 0.f);
            br[k >> 1] = packh2_(v0, v1);
        }
    };

    float wmax[2][2] = {{NEGBIG, NEGBIG}, {NEGBIG, NEGBIG}};

    produce(0, 0);
    __syncthreads();

    for (int tile = 0; tile < NT1; ++tile) {
        const int cur = tile & 1, nxt = cur ^ 1;
        if (tile + 1 < NT1) produce(tile + 1, nxt);

        const uint32_t* Bp = Bf[cur];
        const float* msk = mskS[cur];

#pragma unroll 2
        for (int nbp = 0; nbp < 8; ++nbp) {
            float cA0[4] = {0.f, 0.f, 0.f, 0.f};
            float cA1[4] = {0.f, 0.f, 0.f, 0.f};
            float cB0[4] = {0.f, 0.f, 0.f, 0.f};
            float cB1[4] = {0.f, 0.f, 0.f, 0.f};
            const int nrA = nbp * 16 + g;
            const int nrB = nrA + 8;
#pragma unroll
            for (int ks = 0; ks < 4; ++ks) {
                int ia = nrA * RS + ks * 8 + ctid;
                int ib = nrB * RS + ks * 8 + ctid;
                uint32_t a0 = Bp[ia], a1 = Bp[ia + 4];
                uint32_t b0 = Bp[ib], b1 = Bp[ib + 4];
                MMA_(cA0, Ah[0][ks], a0, a1);
                MMA_(cB0, Ah[0][ks], b0, b1);
                MMA_(cA1, Ah[1][ks], a0, a1);
                MMA_(cB1, Ah[1][ks], b0, b1);
            }
            // deferred epilogue: 2 ops per value (FADD + FMAX)
            float2 mA = *(const float2*)&msk[nbp * 16 + ctid * 2];
            float2 mB = *(const float2*)&msk[nbp * 16 + 8 + ctid * 2];
            wmax[0][0] = fmaxf(wmax[0][0], cA0[0] + mA.x);
            wmax[0][0] = fmaxf(wmax[0][0], cA0[1] + mA.y);
            wmax[0][1] = fmaxf(wmax[0][1], cA0[2] + mA.x);
            wmax[0][1] = fmaxf(wmax[0][1], cA0[3] + mA.y);
            wmax[1][0] = fmaxf(wmax[1][0], cA1[0] + mA.x);
            wmax[1][0] = fmaxf(wmax[1][0], cA1[1] + mA.y);
            wmax[1][1] = fmaxf(wmax[1][1], cA1[2] + mA.x);
            wmax[1][1] = fmaxf(wmax[1][1], cA1[3] + mA.y);
            wmax[0][0] = fmaxf(wmax[0][0], cB0[0] + mB.x);
            wmax[0][0] = fmaxf(wmax[0][0], cB0[1] + mB.y);
            wmax[0][1] = fmaxf(wmax[0][1], cB0[2] + mB.x);
            wmax[0][1] = fmaxf(wmax[0][1], cB0[3] + mB.y);
            wmax[1][0] = fmaxf(wmax[1][0], cB1[0] + mB.x);
            wmax[1][0] = fmaxf(wmax[1][0], cB1[1] + mB.y);
            wmax[1][1] = fmaxf(wmax[1][1], cB1[2] + mB.x);
            wmax[1][1] = fmaxf(wmax[1][1], cB1[3] + mB.y);
        }
        __syncthreads();
    }

#pragma unroll
    for (int mt = 0; mt < 2; mt++)
#pragma unroll
        for (int r = 0; r < 2; r++) {
            float v = wmax[mt][r];
            v = fmaxf(v, __shfl_xor_sync(0xFFFFFFFFu, v, 1));
            v = fmaxf(v, __shfl_xor_sync(0xFFFFFFFFu, v, 2));
            if (ctid == 0)
                d_embpart[blockIdx.y][bs][w * 32 + mt * 16 + r * 8 + g] = v;
        }
}

// =============================================================================
// Kernel 2: one block per s (grid=80); emb = relu(max partials + b2);
// 4 batches share each Wi float4 in regs. Same k-ascending accumulation.
// =============================================================================
__global__ __launch_bounds__(128) void k2_inputgates(
    const float* __restrict__ b2,
    const float* __restrict__ Wi_f, const float* __restrict__ bi_f, const float* __restrict__ bh_f,
    const float* __restrict__ Wi_b, const float* __restrict__ bi_b, const float* __restrict__ bh_b)
{
    __shared__ float embs[Bn][128];
    const int tid = threadIdx.x;
    const int s = blockIdx.x;

    const float b2v = b2[tid];
#pragma unroll
    for (int b = 0; b < Bn; b++) {
        const int bs = b * Sn + s;
        float m = d_embpart[0][bs][tid];
        m = fmaxf(m, d_embpart[1][bs][tid]);
        m = fmaxf(m, d_embpart[2][bs][tid]);
        m = fmaxf(m, d_embpart[3][bs][tid]);
        embs[b][tid] = fmaxf(m + b2v, 0.f);   // deferred bias + relu (empty set -> 0)
    }
    __syncthreads();

#pragma unroll
    for (int dir = 0; dir < 2; dir++) {
        const float* Wi = dir ? Wi_b : Wi_f;
        const float* bi = dir ? bi_b : bi_f;
        const float* bh = dir ? bh_b : bh_f;
        const int t = dir ? (Sn - 1 - s) : s;
#pragma unroll
        for (int rr = 0; rr < 4; rr++) {
            int g = rr * 128 + tid;
            const float* wr = Wi + (size_t)g * 128;
            float a0 = bi[g] + bh[g];
            float acc[Bn] = {a0, a0, a0, a0};
#pragma unroll 8
            for (int k = 0; k < 128; k += 4) {
                float4 w = *(const float4*)(wr + k);
#pragma unroll
                for (int b = 0; b < Bn; b++) {
                    acc[b] = fmaf(w.x, embs[b][k],     acc[b]);
                    acc[b] = fmaf(w.y, embs[b][k + 1], acc[b]);
                    acc[b] = fmaf(w.z, embs[b][k + 2], acc[b]);
                    acc[b] = fmaf(w.w, embs[b][k + 3], acc[b]);
                }
            }
#pragma unroll
            for (int b = 0; b < Bn; b++) d_xg[dir][b][t][g] = acc[b];
        }
    }
}

// =============================================================================
// Kernel 3: LSTM scan, cluster of 4 CTAs per direction. Wh in registers;
// SINGLE cluster sync per step; parity-buffered gate multicast; redundant
// local c/h update. (Exact round-13 proven configuration.)
// =============================================================================
__global__ void __cluster_dims__(4, 1, 1) __launch_bounds__(128, 1)
k3_lstm(const float* __restrict__ Wh_f, const float* __restrict__ Wh_b)
{
    __shared__ __align__(16) float hbuf[Bn * 128];
    __shared__ __align__(16) float gact[2 * 4 * Bn * 128];

    const int t = threadIdx.x;
    const int rank = blockIdx.x & 3;
    const int dir  = blockIdx.x >> 2;
    const float* Wh = dir ? Wh_b : Wh_f;
    const int R = rank * 128 + t;

    uint64_t wreg[64];
    {
        const uint64_t* wr = (const uint64_t*)(Wh + (size_t)R * 128);
#pragma unroll
        for (int i = 0; i < 64; i++) wreg[i] = wr[i];
    }

    for (int i = t; i < Bn * 128; i += 128) hbuf[i] = 0.f;

    float c[Bn];
#pragma unroll
    for (int b = 0; b < Bn; b++) c[b] = 0.f;

    uint32_t rem[4];
#pragma unroll
    for (int r = 0; r < 4; r++)
        rem[r] = mapa_rank_(smem_u32_(&gact[rank * 512 + t]), (uint32_t)r);

    __syncthreads();
    cluster_sync_();

    int par = 0;
    for (int st = 0; st < Sn; ++st) {
        float xin[Bn];
#pragma unroll
        for (int b = 0; b < Bn; b++) xin[b] = d_xg[dir][b][st][R];

        uint64_t acc2[Bn];
#pragma unroll
        for (int b = 0; b < Bn; b++) acc2[b] = 0ull;
#pragma unroll
        for (int k4 = 0; k4 < 32; k4++) {
            const uint64_t w0 = wreg[2 * k4], w1 = wreg[2 * k4 + 1];
#pragma unroll
            for (int b = 0; b < Bn; b++) {
                longlong2 hv = *(const longlong2*)(hbuf + b * 128 + k4 * 4);
                fma2_(acc2[b], w0, (uint64_t)hv.x);
                fma2_(acc2[b], w1, (uint64_t)hv.y);
            }
        }

#pragma unroll
        for (int b = 0; b < Bn; b++) {
            float lo = __uint_as_float((uint32_t)acc2[b]);
            float hi = __uint_as_float((uint32_t)(acc2[b] >> 32));
            float gv = lo + hi + xin[b];
            float av = (rank == 2) ? tanhf(gv) : sigmoid_(gv);
            uint32_t off = (uint32_t)(par * 8192 + b * 512);
#pragma unroll
            for (int r = 0; r < 4; r++) stc_f32_(rem[r] + off, av);
        }
        cluster_sync_();

        const float* gp = gact + par * 2048;
#pragma unroll
        for (int b = 0; b < Bn; b++) {
            float iv = gp[0 * 512 + b * 128 + t];
            float fv = gp[1 * 512 + b * 128 + t];
            float gg = gp[2 * 512 + b * 128 + t];
            float ov = gp[3 * 512 + b * 128 + t];
            float cn = fmaf(fv, c[b], iv * gg);
            c[b] = cn;
            hbuf[b * 128 + t] = ov * tanhf(cn);
        }
        __syncthreads();
        par ^= 1;
    }

    if (rank == 0) {
#pragma unroll
        for (int b = 0; b < Bn; b++) d_hfinal[dir][b][t] = hbuf[b * 128 + t];
    }
}

// =============================================================================
// Kernel 4: head — grid=4 (batch), 1024 threads (thread = eighth W3 row),
// deeper memory parallelism on the latency-bound W3 read.
// =============================================================================
__global__ __launch_bounds__(1024) void k4_head(
    const float* __restrict__ W3, const float* __restrict__ b3,
    const float* __restrict__ W4, const float* __restrict__ b4,
    float* __restrict__ out)
{
    __shared__ float sf[256];
    __shared__ float red[128];
    const int tid = threadIdx.x;
    const int b = blockIdx.x;

    if (tid < 128) {
        sf[tid]       = d_hfinal[0][b][tid];
        sf[128 + tid] = d_hfinal[1][b][tid];
    }
    __syncthreads();

    const int r = tid >> 3, oct = tid & 7;
    const float* w3r = W3 + (size_t)r * 256 + oct * 32;
    const float* xf = sf + oct * 32;

    float a = 0.f;
#pragma unroll
    for (int k = 0; k < 32; k += 4) {
        float4 wv = *(const float4*)(w3r + k);
        a = fmaf(wv.x, xf[k], a);
        a = fmaf(wv.y, xf[k + 1], a);
        a = fmaf(wv.z, xf[k + 2], a);
        a = fmaf(wv.w, xf[k + 3], a);
    }
    a += __shfl_xor_sync(0xFFFFFFFFu, a, 1);
    a += __shfl_xor_sync(0xFFFFFFFFu, a, 2);
    a += __shfl_xor_sync(0xFFFFFFFFu, a, 4);
    if (oct == 0) red[r] = fmaxf(a + b3[r], 0.f) * W4[r];
    __syncthreads();
    for (int off = 64; off > 0; off >>= 1) {
        if (tid < off) red[tid] += red[tid + off];
        __syncthreads();
    }
    if (tid == 0) out[b] = red[0] + b4[0];
}

// =============================================================================
extern "C" void kernel_launch(void* const* d_in, const int* in_sizes, int n_in,
                              void* d_out, int out_size)
{
    const float* slices = (const float*)d_in[0];
    const float* pmask  = (const float*)d_in[1];
    const float* W1   = (const float*)d_in[2];
    const float* b1   = (const float*)d_in[3];
    const float* W2   = (const float*)d_in[4];
    const float* b2   = (const float*)d_in[5];
    const float* Wi_f = (const float*)d_in[6];
    const float* Wh_f = (const float*)d_in[7];
    const float* bi_f = (const float*)d_in[8];
    const float* bh_f = (const float*)d_in[9];
    const float* Wi_b = (const float*)d_in[10];
    const float* Wh_b = (const float*)d_in[11];
    const float* bi_b = (const float*)d_in[12];
    const float* bh_b = (const float*)d_in[13];
    const float* W3   = (const float*)d_in[14];
    const float* b3   = (const float*)d_in[15];
    const float* W4   = (const float*)d_in[16];
    const float* b4   = (const float*)d_in[17];
    float* out = (float*)d_out;

    k1_mma<<<dim3(Bn * Sn, PSPLIT), 128>>>(slices, pmask, W1, b1, W2);
    k2_inputgates<<<Sn, 128>>>(b2, Wi_f, bi_f, bh_f, Wi_b, bi_b, bh_b);
    k3_lstm<<<8, 128>>>(Wh_f, Wh_b);
    k4_head<<<4, 1024>>>(W3, b3, W4, b4, out);
}